// round 7
// baseline (speedup 1.0000x reference)
#include <cuda_runtime.h>
#include <cuda_fp16.h>
#include <math.h>
#include <stdint.h>

#define NP 50000
#define ND 5000
#define FD 512

// ---------------------------------------------------------------------------
// Scratch (u32 units)
// ---------------------------------------------------------------------------
constexpr size_t NPF   = (size_t)NP * FD;        // 25.6M
constexpr size_t NDF   = (size_t)ND * FD;        // 2.56M
constexpr size_t U_SUM_PP = 0;
constexpr size_t U_SUM_DP = U_SUM_PP + NPF;
constexpr size_t U_SUM_PD = U_SUM_DP + NPF;
constexpr size_t U_CNT_PP = U_SUM_PD + NDF;
constexpr size_t U_CNT_DP = U_CNT_PP + NP;
constexpr size_t U_CNT_PD = U_CNT_DP + NP;
constexpr size_t ZERO_END = U_CNT_PD + ND;
// half buffers (u32 = 2 halves)
constexpr size_t U_MH_PP  = (ZERO_END + 1) & ~(size_t)1;
constexpr size_t U_MH_DP  = U_MH_PP + NPF / 2;
constexpr size_t U_MH_PD  = U_MH_DP + NPF / 2;
constexpr size_t U_XH_P   = U_MH_PD + NDF / 2;
constexpr size_t U_XH_D   = U_XH_P + NPF / 2;
constexpr size_t U_XNH_P  = U_XH_D + NDF / 2;
constexpr size_t U_XNH_D  = U_XNH_P + NPF / 2;
constexpr size_t U_REC_P  = U_XNH_D + NDF / 2;   // fp32
constexpr size_t U_REC_D  = U_REC_P + NPF;       // fp32
constexpr size_t U_RECH_P = U_REC_D + NDF;
constexpr size_t U_RECH_D = U_RECH_P + NPF / 2;
constexpr size_t U_WCOMB  = U_RECH_D + NDF / 2;
constexpr size_t U_WRPP   = U_WCOMB + (size_t)FD * FD / 2;
constexpr size_t U_WRDP   = U_WRPP + (size_t)FD * FD / 2;
constexpr size_t U_WRPD   = U_WRDP + (size_t)FD * FD / 2;
constexpr size_t U_WLPD   = U_WRPD + (size_t)FD * FD / 2;
constexpr size_t U_WDECP  = U_WLPD + (size_t)FD * FD / 2;
constexpr size_t U_WDECD  = U_WDECP + (size_t)FD * FD;
constexpr size_t U_BSUM   = U_WDECD + (size_t)FD * FD;
constexpr size_t U_TOTAL  = U_BSUM + FD;

__device__ __align__(16) unsigned g_scratch[U_TOTAL];

__device__ __forceinline__ unsigned pack_h2(float a, float b) {
    __half2 h = __floats2half2_rn(a, b);
    return *reinterpret_cast<unsigned*>(&h);
}

// ---------------------------------------------------------------------------
// elementwise kernels
// ---------------------------------------------------------------------------
__global__ void zero_kernel(float4* p, size_t n4) {
    size_t i = (size_t)blockIdx.x * blockDim.x + threadIdx.x;
    size_t stride = (size_t)gridDim.x * blockDim.x;
    for (; i < n4; i += stride) p[i] = make_float4(0.f, 0.f, 0.f, 0.f);
}

struct PrepArgs {
    const float *wlpp, *wldp, *wrpp, *wrdp, *wrpd, *wlpd, *wdecp, *wdecd, *bpp, *bdp;
    unsigned *o_wcomb, *o_wrpp, *o_wrdp, *o_wrpd, *o_wlpd, *o_wdecp, *o_wdecd;
    float* o_bsum;
};

__global__ void prep_kernel(PrepArgs a) {
    int i = blockIdx.x * blockDim.x + threadIdx.x;
    const int nh = FD * FD / 2;          // u32 count for a 512x512 half matrix
    if (i < nh) {
        int j = 2 * i;
        a.o_wcomb[i] = pack_h2(a.wlpp[j] + a.wldp[j], a.wlpp[j + 1] + a.wldp[j + 1]);
        a.o_wrpp[i]  = pack_h2(a.wrpp[j], a.wrpp[j + 1]);
        a.o_wrdp[i]  = pack_h2(a.wrdp[j], a.wrdp[j + 1]);
        a.o_wrpd[i]  = pack_h2(a.wrpd[j], a.wrpd[j + 1]);
        a.o_wlpd[i]  = pack_h2(a.wlpd[j], a.wlpd[j + 1]);
    }
    if (i < 2 * nh) {
        int j = 2 * i;
        a.o_wdecp[i] = pack_h2(a.wdecp[j], a.wdecp[j + 1]);
        a.o_wdecd[i] = pack_h2(a.wdecd[j], a.wdecd[j + 1]);
    }
    if (i < FD) a.o_bsum[i] = a.bpp[i] + a.bdp[i];
}

struct ScatArgs {
    const int* ei[3];
    const float* x[3];
    float* sum[3];
    float* cnt[3];
    int E[3];
    int b0, b01;   // block prefix bounds
};

__global__ void scatter_all(ScatArgs a) {
    int b = blockIdx.x, t;
    if (b < a.b0)       { t = 0; }
    else if (b < a.b01) { t = 1; b -= a.b0; }
    else                { t = 2; b -= a.b01; }
    int e = b * 2 + (threadIdx.x >> 7);
    if (e >= a.E[t]) return;
    int lane = threadIdx.x & 127;
    int src = a.ei[t][e];
    int dst = a.ei[t][(size_t)a.E[t] + e];
    float4 v = *(const float4*)(a.x[t] + (size_t)src * FD + lane * 4);
    float* o = a.sum[t] + (size_t)dst * FD + lane * 4;
    asm volatile("red.global.add.v4.f32 [%0], {%1,%2,%3,%4};"
                 :: "l"(o), "f"(v.x), "f"(v.y), "f"(v.z), "f"(v.w) : "memory");
    if (lane == 0) atomicAdd(a.cnt[t] + dst, 1.0f);
}

struct FinArgs {
    const float4* sum[3];
    const float* cnt[3];
    uint2* outh[3];
    size_t n[3];   // float4 count per region
};

// mean + fp32->fp16, sums -> half buffers
__global__ void finalize_all(FinArgs a) {
    size_t i = (size_t)blockIdx.x * blockDim.x + threadIdx.x;
    int t = 0;
    if (i >= a.n[0]) { i -= a.n[0]; t = 1; }
    if (t == 1 && i >= a.n[1]) { i -= a.n[1]; t = 2; }
    if (t == 2 && i >= a.n[2]) return;
    int row = (int)(i >> 7);                  // 128 float4 per row
    float iv = 1.0f / fmaxf(a.cnt[t][row], 1.0f);
    float4 v = a.sum[t][i];
    a.outh[t][i] = make_uint2(pack_h2(v.x * iv, v.y * iv),
                              pack_h2(v.z * iv, v.w * iv));
}

// l2 norm rows -> half (out_n), optional plain half copy (out_p); fp32 in.
struct NormArgs {
    const float* in[2];
    uint2* out_n[2];
    uint2* out_p[2];   // may be null
    int rows[2];
};

__global__ void cvtnorm_all(NormArgs a) {
    int row = (int)(((size_t)blockIdx.x * blockDim.x + threadIdx.x) >> 5);
    int t = 0;
    if (row >= a.rows[0]) { row -= a.rows[0]; t = 1; }
    if (t == 1 && row >= a.rows[1]) return;
    int lane = threadIdx.x & 31;
    const float4* p = (const float4*)(a.in[t] + (size_t)row * FD);
    float4 v[4];
    float ss = 0.f;
#pragma unroll
    for (int i = 0; i < 4; i++) {
        v[i] = p[lane + 32 * i];
        ss += v[i].x * v[i].x + v[i].y * v[i].y + v[i].z * v[i].z + v[i].w * v[i].w;
    }
#pragma unroll
    for (int o = 16; o > 0; o >>= 1) ss += __shfl_xor_sync(0xffffffffu, ss, o);
    float inv = 1.0f / fmaxf(sqrtf(ss), 1e-12f);
    if (a.out_p[t]) {
        uint2* q = a.out_p[t] + (size_t)row * 128;
#pragma unroll
        for (int i = 0; i < 4; i++)
            q[lane + 32 * i] = make_uint2(pack_h2(v[i].x, v[i].y),
                                          pack_h2(v[i].z, v[i].w));
    }
    uint2* qn = a.out_n[t] + (size_t)row * 128;
#pragma unroll
    for (int i = 0; i < 4; i++)
        qn[lane + 32 * i] = make_uint2(pack_h2(v[i].x * inv, v[i].y * inv),
                                       pack_h2(v[i].z * inv, v[i].w * inv));
}

// ---------------------------------------------------------------------------
// fp16 mma.sync GEMM, 4-stage cp.async pipeline, 2 fused problems per launch.
//   C[M,512] = sum_s A_s @ B_s^T + bias   (A,B half; C fp32)
// block 128x256x32(half), grid.y = 2 N-tiles, 8 warps (2x4), warp 64x64,
// m16n8k16.
// ---------------------------------------------------------------------------
struct SegH {
    const __half* A[3];
    const __half* B[3];
    int ldb[3];
};
struct ProbH {
    SegH segs;
    int nseg;
    const float* bias;
    float* C;
    int M;
};

#define SROW_H 40                         // 32 halves + 8 pad (80B rows)
#define A_BYTES_H (128 * SROW_H * 2)      // 10240
#define B_BYTES_H (256 * SROW_H * 2)      // 20480
#define STG_H (A_BYTES_H + B_BYTES_H)     // 30720
#define GEMM_SMEM (4 * STG_H)             // 122880

__device__ __forceinline__ void cp16s(uint32_t dst_smem, const void* src, int sz) {
    asm volatile("cp.async.cg.shared.global [%0], [%1], 16, %2;"
                 :: "r"(dst_smem), "l"(src), "r"(sz));
}
__device__ __forceinline__ uint32_t smem_u32(const void* p) {
    uint32_t a;
    asm("{ .reg .u64 t; cvta.to.shared.u64 t, %1; cvt.u32.u64 %0, t; }"
        : "=r"(a) : "l"(p));
    return a;
}

extern __shared__ __align__(128) unsigned char hsm[];

__global__ __launch_bounds__(256, 1) void gemm_h(ProbH p0, ProbH p1, int split) {
    const bool first = (blockIdx.x < (unsigned)split);
    ProbH p = first ? p0 : p1;
    const int bm = (first ? blockIdx.x : blockIdx.x - split) * 128;
    const int bn = blockIdx.y * 256;     // N tile (FD=512 -> gridDim.y=2)

    const int tid  = threadIdx.x;
    const int lane = tid & 31;
    const int warp = tid >> 5;
    const int wm = warp >> 2;            // 0..1
    const int wn = warp & 3;             // 0..3
    const int g  = lane >> 2;            // 0..7
    const int t4 = lane & 3;             // 0..3

    const uint32_t dyn = smem_u32(hsm);

    float acc[4][8][4];
#pragma unroll
    for (int mi = 0; mi < 4; mi++)
#pragma unroll
        for (int ni = 0; ni < 8; ni++)
#pragma unroll
            for (int r = 0; r < 4; r++) acc[mi][ni][r] = 0.f;

    const int NKB = p.nseg * (FD / 32);

    auto issue = [&](int kb) {
        const int st   = kb & 3;
        const int s    = kb >> 4;
        const int koff = (kb & 15) * 32;
        const __half* Ab = p.segs.A[s];
        const __half* Bb = p.segs.B[s];
        const int ldb = p.segs.ldb[s];
        const uint32_t abase = dyn + st * STG_H;
        const uint32_t bbase = abase + A_BYTES_H;
#pragma unroll
        for (int i = 0; i < 2; i++) {            // A: 512 x 16B
            int u = tid + i * 256;
            int row = u >> 2, c16 = u & 3;
            int r = bm + row;
            bool ok = r < p.M;
            cp16s(abase + (uint32_t)(row * (SROW_H * 2) + c16 * 16),
                  Ab + (size_t)(ok ? r : 0) * FD + koff + c16 * 8, ok ? 16 : 0);
        }
#pragma unroll
        for (int i = 0; i < 4; i++) {            // B: 1024 x 16B
            int u = tid + i * 256;
            int row = u >> 2, c16 = u & 3;
            cp16s(bbase + (uint32_t)(row * (SROW_H * 2) + c16 * 16),
                  Bb + (size_t)(bn + row) * ldb + koff + c16 * 8, 16);
        }
        asm volatile("cp.async.commit_group;");
    };

    issue(0);
    if (NKB > 1) issue(1);
    if (NKB > 2) issue(2);

    for (int c = 0; c < NKB; c++) {
        const int st = c & 3;
        if (c + 3 < NKB) issue(c + 3);
        const int rem = NKB - 1 - c;
        if (rem >= 3)      asm volatile("cp.async.wait_group 3;");
        else if (rem == 2) asm volatile("cp.async.wait_group 2;");
        else if (rem == 1) asm volatile("cp.async.wait_group 1;");
        else               asm volatile("cp.async.wait_group 0;");
        __syncthreads();

        const __half* As = (const __half*)(hsm + st * STG_H);
        const __half* Bs = (const __half*)(hsm + st * STG_H + A_BYTES_H);
        const int m0 = wm * 64 + g;
        const int n0 = wn * 64 + g;

#pragma unroll
        for (int ks = 0; ks < 2; ks++) {
            const int kh = ks * 16 + t4 * 2;
            unsigned a[4][4], b[8][2];
#pragma unroll
            for (int mi = 0; mi < 4; mi++) {
                const __half* r0 = As + (m0 + mi * 16) * SROW_H + kh;
                a[mi][0] = *(const unsigned*)(r0);
                a[mi][1] = *(const unsigned*)(r0 + 8 * SROW_H);
                a[mi][2] = *(const unsigned*)(r0 + 8);
                a[mi][3] = *(const unsigned*)(r0 + 8 * SROW_H + 8);
            }
#pragma unroll
            for (int ni = 0; ni < 8; ni++) {
                const __half* r0 = Bs + (n0 + ni * 8) * SROW_H + kh;
                b[ni][0] = *(const unsigned*)(r0);
                b[ni][1] = *(const unsigned*)(r0 + 8);
            }
#pragma unroll
            for (int mi = 0; mi < 4; mi++)
#pragma unroll
                for (int ni = 0; ni < 8; ni++) {
                    asm volatile(
                        "mma.sync.aligned.m16n8k16.row.col.f32.f16.f16.f32 "
                        "{%0,%1,%2,%3}, {%4,%5,%6,%7}, {%8,%9}, {%0,%1,%2,%3};"
                        : "+f"(acc[mi][ni][0]), "+f"(acc[mi][ni][1]),
                          "+f"(acc[mi][ni][2]), "+f"(acc[mi][ni][3])
                        : "r"(a[mi][0]), "r"(a[mi][1]), "r"(a[mi][2]),
                          "r"(a[mi][3]), "r"(b[ni][0]), "r"(b[ni][1]));
                }
        }
        __syncthreads();
    }

    // epilogue
#pragma unroll
    for (int ni = 0; ni < 8; ni++) {
        const int c = bn + wn * 64 + ni * 8 + t4 * 2;
        const float bb0 = p.bias[c];
        const float bb1 = p.bias[c + 1];
#pragma unroll
        for (int mi = 0; mi < 4; mi++) {
            const int r0 = bm + wm * 64 + mi * 16 + g;
            if (r0 < p.M)
                *(float2*)(p.C + (size_t)r0 * FD + c) =
                    make_float2(acc[mi][ni][0] + bb0, acc[mi][ni][1] + bb1);
            const int r1 = r0 + 8;
            if (r1 < p.M)
                *(float2*)(p.C + (size_t)r1 * FD + c) =
                    make_float2(acc[mi][ni][2] + bb0, acc[mi][ni][3] + bb1);
        }
    }
}

// ---------------------------------------------------------------------------
// kernel_launch
// ---------------------------------------------------------------------------
extern "C" void kernel_launch(void* const* d_in, const int* in_sizes, int n_in,
                              void* d_out, int out_size) {
    const float* x_paper   = (const float*)d_in[0];
    const float* x_dataset = (const float*)d_in[1];
    const int*   ei_pp     = (const int*)d_in[2];
    const int*   ei_pd     = (const int*)d_in[3];
    const int*   ei_dp     = (const int*)d_in[4];
    const float* Wl_pp = (const float*)d_in[5];
    const float* Wr_pp = (const float*)d_in[6];
    const float* b_pp  = (const float*)d_in[7];
    const float* Wl_pd = (const float*)d_in[8];
    const float* Wr_pd = (const float*)d_in[9];
    const float* b_pd  = (const float*)d_in[10];
    const float* Wl_dp = (const float*)d_in[11];
    const float* Wr_dp = (const float*)d_in[12];
    const float* b_dp  = (const float*)d_in[13];
    const float* Wdec_p = (const float*)d_in[14];
    const float* bdec_p = (const float*)d_in[15];
    const float* Wdec_d = (const float*)d_in[16];
    const float* bdec_d = (const float*)d_in[17];

    const int Epp = in_sizes[2] / 2;
    const int Epd = in_sizes[3] / 2;
    const int Edp = in_sizes[4] / 2;

    float* out = (float*)d_out;

    unsigned* base = nullptr;
    cudaGetSymbolAddress((void**)&base, g_scratch);
    float*    sum_pp = (float*)(base + U_SUM_PP);
    float*    sum_dp = (float*)(base + U_SUM_DP);
    float*    sum_pd = (float*)(base + U_SUM_PD);
    float*    cnt_pp = (float*)(base + U_CNT_PP);
    float*    cnt_dp = (float*)(base + U_CNT_DP);
    float*    cnt_pd = (float*)(base + U_CNT_PD);
    __half*   mh_pp  = (__half*)(base + U_MH_PP);
    __half*   mh_dp  = (__half*)(base + U_MH_DP);
    __half*   mh_pd  = (__half*)(base + U_MH_PD);
    __half*   xh_p   = (__half*)(base + U_XH_P);
    __half*   xh_d   = (__half*)(base + U_XH_D);
    __half*   xnh_p  = (__half*)(base + U_XNH_P);
    __half*   xnh_d  = (__half*)(base + U_XNH_D);
    float*    rec_p  = (float*)(base + U_REC_P);
    float*    rec_d  = (float*)(base + U_REC_D);
    __half*   rech_p = (__half*)(base + U_RECH_P);
    __half*   rech_d = (__half*)(base + U_RECH_D);
    __half*   wcomb  = (__half*)(base + U_WCOMB);
    __half*   wrpp   = (__half*)(base + U_WRPP);
    __half*   wrdp   = (__half*)(base + U_WRDP);
    __half*   wrpd   = (__half*)(base + U_WRPD);
    __half*   wlpd   = (__half*)(base + U_WLPD);
    __half*   wdecp  = (__half*)(base + U_WDECP);
    __half*   wdecd  = (__half*)(base + U_WDECD);
    float*    bsum   = (float*)(base + U_BSUM);

    cudaFuncSetAttribute(gemm_h, cudaFuncAttributeMaxDynamicSharedMemorySize,
                         GEMM_SMEM);

    // 1) zero sums + counts
    zero_kernel<<<4096, 256>>>((float4*)base, ZERO_END / 4);

    // 2) weight/bias prep
    PrepArgs pa;
    pa.wlpp = Wl_pp; pa.wldp = Wl_dp; pa.wrpp = Wr_pp; pa.wrdp = Wr_dp;
    pa.wrpd = Wr_pd; pa.wlpd = Wl_pd; pa.wdecp = Wdec_p; pa.wdecd = Wdec_d;
    pa.bpp = b_pp; pa.bdp = b_dp;
    pa.o_wcomb = (unsigned*)wcomb; pa.o_wrpp = (unsigned*)wrpp;
    pa.o_wrdp = (unsigned*)wrdp; pa.o_wrpd = (unsigned*)wrpd;
    pa.o_wlpd = (unsigned*)wlpd; pa.o_wdecp = (unsigned*)wdecp;
    pa.o_wdecd = (unsigned*)wdecd; pa.o_bsum = bsum;
    prep_kernel<<<(FD * FD + 255) / 256, 256>>>(pa);

    // 3) all scatters in one launch
    ScatArgs sa;
    sa.ei[0] = ei_pp; sa.x[0] = x_paper;   sa.sum[0] = sum_pp; sa.cnt[0] = cnt_pp; sa.E[0] = Epp;
    sa.ei[1] = ei_dp; sa.x[1] = x_dataset; sa.sum[1] = sum_dp; sa.cnt[1] = cnt_dp; sa.E[1] = Edp;
    sa.ei[2] = ei_pd; sa.x[2] = x_paper;   sa.sum[2] = sum_pd; sa.cnt[2] = cnt_pd; sa.E[2] = Epd;
    int nb0 = (Epp + 1) / 2, nb1 = (Edp + 1) / 2, nb2 = (Epd + 1) / 2;
    sa.b0 = nb0; sa.b01 = nb0 + nb1;
    scatter_all<<<nb0 + nb1 + nb2, 256>>>(sa);

    // 4) finalize all (mean -> half)
    FinArgs fa;
    fa.sum[0] = (const float4*)sum_pp; fa.cnt[0] = cnt_pp; fa.outh[0] = (uint2*)mh_pp; fa.n[0] = (size_t)NP * 128;
    fa.sum[1] = (const float4*)sum_dp; fa.cnt[1] = cnt_dp; fa.outh[1] = (uint2*)mh_dp; fa.n[1] = (size_t)NP * 128;
    fa.sum[2] = (const float4*)sum_pd; fa.cnt[2] = cnt_pd; fa.outh[2] = (uint2*)mh_pd; fa.n[2] = (size_t)ND * 128;
    size_t ftot = fa.n[0] + fa.n[1] + fa.n[2];
    finalize_all<<<(int)((ftot + 255) / 256), 256>>>(fa);

    // 5) x -> half (plain + normalized)
    NormArgs na;
    na.in[0] = x_paper;   na.out_n[0] = (uint2*)xnh_p; na.out_p[0] = (uint2*)xh_p; na.rows[0] = NP;
    na.in[1] = x_dataset; na.out_n[1] = (uint2*)xnh_d; na.out_p[1] = (uint2*)xh_d; na.rows[1] = ND;
    cvtnorm_all<<<((NP + ND) * 32 + 255) / 256, 256>>>(na);

    const int gp = (NP + 127) / 128;   // 391
    const int gd = (ND + 127) / 128;   // 40
    dim3 ggrid(gp + gd, FD / 256);     // x: fused M-tiles, y: 2 N-tiles

    // 6) encoder GEMMs (fused)
    ProbH e0 = {}, e1 = {};
    e0.segs.A[0] = mh_pp; e0.segs.B[0] = wrpp;  e0.segs.ldb[0] = FD;
    e0.segs.A[1] = mh_dp; e0.segs.B[1] = wrdp;  e0.segs.ldb[1] = FD;
    e0.segs.A[2] = xh_p;  e0.segs.B[2] = wcomb; e0.segs.ldb[2] = FD;
    e0.nseg = 3; e0.bias = bsum; e0.C = rec_p; e0.M = NP;
    e1.segs.A[0] = mh_pd; e1.segs.B[0] = wrpd; e1.segs.ldb[0] = FD;
    e1.segs.A[1] = xh_d;  e1.segs.B[1] = wlpd; e1.segs.ldb[1] = FD;
    e1.nseg = 2; e1.bias = b_pd; e1.C = rec_d; e1.M = ND;
    gemm_h<<<ggrid, 256, GEMM_SMEM>>>(e0, e1, gp);

    // 7) rec -> half normalized
    NormArgs nr;
    nr.in[0] = rec_p; nr.out_n[0] = (uint2*)rech_p; nr.out_p[0] = nullptr; nr.rows[0] = NP;
    nr.in[1] = rec_d; nr.out_n[1] = (uint2*)rech_d; nr.out_p[1] = nullptr; nr.rows[1] = ND;
    cvtnorm_all<<<((NP + ND) * 32 + 255) / 256, 256>>>(nr);

    // 8) decoder GEMMs (fused)
    ProbH d0 = {}, d1 = {};
    d0.segs.A[0] = rech_p; d0.segs.B[0] = wdecp;      d0.segs.ldb[0] = 2 * FD;
    d0.segs.A[1] = xnh_p;  d0.segs.B[1] = wdecp + FD; d0.segs.ldb[1] = 2 * FD;
    d0.nseg = 2; d0.bias = bdec_p; d0.C = out; d0.M = NP;
    d1.segs.A[0] = rech_d; d1.segs.B[0] = wdecd;      d1.segs.ldb[0] = 2 * FD;
    d1.segs.A[1] = xnh_d;  d1.segs.B[1] = wdecd + FD; d1.segs.ldb[1] = 2 * FD;
    d1.nseg = 2; d1.bias = bdec_d; d1.C = out + (size_t)NP * FD; d1.M = ND;
    gemm_h<<<ggrid, 256, GEMM_SMEM>>>(d0, d1, gp);
}